// round 17
// baseline (speedup 1.0000x reference)
#include <cuda_runtime.h>
#include <math_constants.h>
#include <cstdint>

#define E_DIM 256
#define T_DIM 1024
#define NH 8
#define HD 32
#define B_DIM 8
#define BHTOT 64   // B*NH

// Scratch (no allocations allowed). tf32-bit floats, "quad" fragment layouts:
// within each 32-channel block, channel d (ks=d>>3, tig=d&3, half=(d>>2)&1)
// sits at position tig*8 + ks*2 + half  -> every MMA fragment is contiguous.
//  g_q, g_k : [bh][t][qq(d)]
//  g_v      : [bh][d][t'], t' quad per 32-token block (token u at (u>>1)*8+ks*2+(u&1))
//  g_ao     : [bh][t][qq(d)]
//  g_xt     : [tensor][b][t][qq(e)]  (quad per 32-channel chunk)
//  g_wp     : [4][m][qq(k)]
//  g_msk    : mask * log2(e)
__device__ float g_q  [BHTOT * T_DIM * HD];
__device__ float g_k  [BHTOT * T_DIM * HD];
__device__ float g_v  [BHTOT * T_DIM * HD];
__device__ float g_ao [BHTOT * T_DIM * HD];
__device__ float g_xt [3u * B_DIM * T_DIM * E_DIM];
__device__ float g_wp [4 * E_DIM * E_DIM];
__device__ float g_msk[T_DIM * T_DIM];

// ===========================================================================
__device__ __forceinline__ uint32_t f2tf(float x) {
    uint32_t r;
    asm("cvt.rna.tf32.f32 %0, %1;" : "=r"(r) : "f"(x));
    return r;
}
__device__ __forceinline__ float u2f(uint32_t x) { return __uint_as_float(x); }
__device__ __forceinline__ float ex2(float x) {
    float r;
    asm("ex2.approx.f32 %0, %1;" : "=f"(r) : "f"(x));
    return r;
}

__device__ __forceinline__ void mma16n8k8(float c[4], const uint32_t a[4],
                                          uint32_t b0, uint32_t b1) {
    asm volatile(
        "mma.sync.aligned.m16n8k8.row.col.f32.tf32.tf32.f32 "
        "{%0,%1,%2,%3}, {%4,%5,%6,%7}, {%8,%9}, {%0,%1,%2,%3};"
        : "+f"(c[0]), "+f"(c[1]), "+f"(c[2]), "+f"(c[3])
        : "r"(a[0]), "r"(a[1]), "r"(a[2]), "r"(a[3]), "r"(b0), "r"(b1));
}

// quad position within a 32-block for channel e
__device__ __forceinline__ int qqpos(int e) {
    return (e & ~31) + (e & 3) * 8 + (((e >> 3) & 3) << 1) + ((e >> 2) & 1);
}
// inverse: source channel for quad position p
__device__ __forceinline__ int srcq(int p) {
    return (p & ~31) + (((p & 7) >> 1) << 3) + ((p >> 3) & 3) + ((p & 1) << 2);
}

__device__ __forceinline__ uint32_t smem_u32(const void* p) {
    uint32_t a;
    asm("{ .reg .u64 t; cvta.to.shared.u64 t, %1; cvt.u32.u64 %0, t; }" : "=r"(a) : "l"(p));
    return a;
}
__device__ __forceinline__ void cp_async16(uint32_t dst, const void* src) {
    asm volatile("cp.async.ca.shared.global [%0], [%1], 16;" :: "r"(dst), "l"(src));
}
#define CP_COMMIT() asm volatile("cp.async.commit_group;" ::: "memory")
#define CP_WAIT0()  asm volatile("cp.async.wait_group 0;" ::: "memory")
#define CP_WAIT1()  asm volatile("cp.async.wait_group 1;" ::: "memory")

// ---------------------------------------------------------------------------
// Mask pre-scale by log2(e).
// ---------------------------------------------------------------------------
__global__ __launch_bounds__(256) void mcvt_kernel(const float* __restrict__ m,
                                                   float* __restrict__ out)
{
    const float L2E = 1.4426950408889634f;
    size_t i = ((size_t)blockIdx.x * 256 + threadIdx.x) * 4;
    float4 v = *(const float4*)(m + i);
    v.x *= L2E; v.y *= L2E; v.z *= L2E; v.w *= L2E;
    *(float4*)(out + i) = v;
}

// ---------------------------------------------------------------------------
// Weight pre-convert: W[m][k] fp32 -> g_wp[wi][m][qq(k)] tf32 bits.
// ---------------------------------------------------------------------------
__global__ void wcvt_kernel(const float* __restrict__ Wq, const float* __restrict__ Wk,
                            const float* __restrict__ Wv, const float* __restrict__ Wo,
                            float* __restrict__ out)
{
    const float* W = (blockIdx.y == 0) ? Wq : (blockIdx.y == 1) ? Wk
                   : (blockIdx.y == 2) ? Wv : Wo;
    int m = blockIdx.x;
    int p = threadIdx.x * 4;
    const float* row = W + (size_t)m * E_DIM;
    float4 v;
    v.x = u2f(f2tf(row[srcq(p + 0)]));
    v.y = u2f(f2tf(row[srcq(p + 1)]));
    v.z = u2f(f2tf(row[srcq(p + 2)]));
    v.w = u2f(f2tf(row[srcq(p + 3)]));
    *(float4*)(out + ((size_t)blockIdx.y * E_DIM + m) * E_DIM + p) = v;
}

// ---------------------------------------------------------------------------
// Input transpose+convert: X[b][e][t] fp32 -> g_xt[tensor][b][t][qq(e)] tf32.
// ---------------------------------------------------------------------------
__global__ __launch_bounds__(256) void xt_kernel(
    const float* __restrict__ q, const float* __restrict__ k,
    const float* __restrict__ v, float* __restrict__ out)
{
    __shared__ float Ts[64][65];
    const int tz = blockIdx.z;
    const int tensor = tz >> 3, b = tz & 7;
    const float* X = (tensor == 0) ? q : (tensor == 1) ? k : v;
    const int e0 = blockIdx.y * 64, t0 = blockIdx.x * 64;
    const int tid = threadIdx.x;

    #pragma unroll
    for (int j = 0; j < 4; j++) {
        int e  = (tid >> 4) + j * 16;
        int t4 = (tid & 15) * 4;
        float4 val = *(const float4*)&X[((size_t)b * E_DIM + e0 + e) * T_DIM + t0 + t4];
        Ts[e][t4 + 0] = val.x; Ts[e][t4 + 1] = val.y;
        Ts[e][t4 + 2] = val.z; Ts[e][t4 + 3] = val.w;
    }
    __syncthreads();
    float* ob = out + (size_t)tensor * (B_DIM * T_DIM * E_DIM)
              + ((size_t)b * T_DIM + t0) * E_DIM + e0;
    #pragma unroll
    for (int j = 0; j < 8; j++) {
        int t = (tid >> 5) + j * 8;
        int e = tid & 31;
        ob[(size_t)t * E_DIM + qqpos(e)]      = u2f(f2tf(Ts[e][t]));
        ob[(size_t)t * E_DIM + qqpos(e + 32)] = u2f(f2tf(Ts[e + 32][t]));
    }
}

// ---------------------------------------------------------------------------
// QKV projection, cp.async double-buffered, quad operands (LDS.128 frags).
// Block 256 (8 warps: 2m x 4n), tile M=64 x N=256, K-chunk 32, 8 chunks.
// Smem: Xs[2][256][36] + Ws[2][64][36] = 92160 B (dynamic).
// ---------------------------------------------------------------------------
#define QKV_STAGE(KK0, BUF) do {                                               \
    _Pragma("unroll")                                                          \
    for (int j = 0; j < 8; j++) {                                              \
        int r = (tid >> 3) + j * 32;                                           \
        int seg = tid & 7;                                                     \
        cp_async16(xs_a + (((BUF) * 256 + r) * 36 + seg * 4) * 4,              \
                   Xb + (size_t)(n0 + r) * E_DIM + (KK0) + seg * 4);           \
    }                                                                          \
    _Pragma("unroll")                                                          \
    for (int j = 0; j < 2; j++) {                                              \
        int r = (tid >> 3) + j * 32;                                           \
        int seg = tid & 7;                                                     \
        cp_async16(ws_a + (((BUF) * 64 + r) * 36 + seg * 4) * 4,               \
                   Wm + (size_t)(m0 + r) * E_DIM + (KK0) + seg * 4);           \
    }                                                                          \
    CP_COMMIT();                                                               \
} while (0)

__global__ __launch_bounds__(256) void proj_qkv_kernel(
    const float* __restrict__ Xt, const float* __restrict__ Wp,
    const float* __restrict__ bq, const float* __restrict__ bk,
    const float* __restrict__ bv,
    float* __restrict__ Yq, float* __restrict__ Yk, float* __restrict__ Yv,
    float scale0)
{
    extern __shared__ float sm[];
    float* Xs  = sm;                 // [2][256][36]
    float* Wsm = sm + 2 * 256 * 36;  // [2][64][36]

    const int zz = blockIdx.z;
    const int b = zz & 7, which = zz >> 3;
    const float* Xb = Xt + (((size_t)which * B_DIM + b) * T_DIM) * E_DIM;
    const float* Wm = Wp + (size_t)which * E_DIM * E_DIM;
    const float* bias = (which == 0) ? bq : (which == 1) ? bk : bv;
    float* Y = (which == 0) ? Yq : (which == 1) ? Yk : Yv;
    const float scale = (which == 0) ? scale0 : 1.0f;

    const int m0 = blockIdx.y * 64;
    const int n0 = blockIdx.x * 256;
    const int tid = threadIdx.x;
    const int w = tid >> 5, l = tid & 31;
    const int wm = w >> 2, wn = w & 3;
    const int grp = l >> 2, tig = l & 3;

    const uint32_t xs_a = smem_u32(Xs);
    const uint32_t ws_a = smem_u32(Wsm);

    float acc[2][8][4];
    #pragma unroll
    for (int mt = 0; mt < 2; mt++)
        #pragma unroll
        for (int nt = 0; nt < 8; nt++)
            #pragma unroll
            for (int j = 0; j < 4; j++) acc[mt][nt][j] = 0.f;

    QKV_STAGE(0, 0);

    for (int c = 0; c < 8; c++) {
        const int buf = c & 1;
        if (c < 7) { QKV_STAGE((c + 1) * 32, buf ^ 1); CP_WAIT1(); }
        else       { CP_WAIT0(); }
        __syncthreads();

        // ---- A fragments: 8x LDS.128 give all 4 ks x 2 m-tiles ----
        const float* wb = Wsm + (size_t)(buf * 64 + wm * 32 + grp) * 36 + tig * 8;
        uint4 wA  = *(const uint4*)(wb);
        uint4 wAb = *(const uint4*)(wb + 4);
        uint4 wB  = *(const uint4*)(wb + 8 * 36);
        uint4 wBb = *(const uint4*)(wb + 8 * 36 + 4);
        uint4 wC  = *(const uint4*)(wb + 16 * 36);
        uint4 wCb = *(const uint4*)(wb + 16 * 36 + 4);
        uint4 wD  = *(const uint4*)(wb + 24 * 36);
        uint4 wDb = *(const uint4*)(wb + 24 * 36 + 4);
        uint32_t a0[4][4] = {{wA.x, wB.x, wA.y, wB.y}, {wA.z, wB.z, wA.w, wB.w},
                             {wAb.x, wBb.x, wAb.y, wBb.y}, {wAb.z, wBb.z, wAb.w, wBb.w}};
        uint32_t a1[4][4] = {{wC.x, wD.x, wC.y, wD.y}, {wC.z, wD.z, wC.w, wD.w},
                             {wCb.x, wDb.x, wCb.y, wDb.y}, {wCb.z, wDb.z, wCb.w, wDb.w}};

        #pragma unroll
        for (int nt = 0; nt < 8; nt++) {
            const float* xb = Xs + (size_t)(buf * 256 + wn * 64 + nt * 8 + grp) * 36 + tig * 8;
            uint4 x0 = *(const uint4*)(xb);
            uint4 x1 = *(const uint4*)(xb + 4);
            mma16n8k8(acc[0][nt], a0[0], x0.x, x0.y);
            mma16n8k8(acc[1][nt], a1[0], x0.x, x0.y);
            mma16n8k8(acc[0][nt], a0[1], x0.z, x0.w);
            mma16n8k8(acc[1][nt], a1[1], x0.z, x0.w);
            mma16n8k8(acc[0][nt], a0[2], x1.x, x1.y);
            mma16n8k8(acc[1][nt], a1[2], x1.x, x1.y);
            mma16n8k8(acc[0][nt], a0[3], x1.z, x1.w);
            mma16n8k8(acc[1][nt], a1[3], x1.z, x1.w);
        }
        __syncthreads();
    }

    // ---- epilogue (tf32 quad outputs) ----
    const int head = (m0 + wm * 32) >> 5;
    #pragma unroll
    for (int mt = 0; mt < 2; mt++) {
        int r0 = m0 + wm * 32 + mt * 16 + grp;
        int r1 = r0 + 8;
        float bv0 = bias[r0], bv1 = bias[r1];
        #pragma unroll
        for (int nt = 0; nt < 8; nt++) {
            int c = n0 + wn * 64 + nt * 8 + 2 * tig;
            float v00 = (acc[mt][nt][0] + bv0) * scale;
            float v01 = (acc[mt][nt][1] + bv0) * scale;
            float v10 = (acc[mt][nt][2] + bv1) * scale;
            float v11 = (acc[mt][nt][3] + bv1) * scale;
            uint32_t t00 = f2tf(v00), t01 = f2tf(v01);
            uint32_t t10 = f2tf(v10), t11 = f2tf(v11);
            if (which != 2) {
                // q/k quad: pair channels (d, d+4) via shfl 16
                uint32_t u00 = __shfl_xor_sync(0xffffffffu, t00, 16);
                uint32_t u01 = __shfl_xor_sync(0xffffffffu, t01, 16);
                uint32_t u10 = __shfl_xor_sync(0xffffffffu, t10, 16);
                uint32_t u11 = __shfl_xor_sync(0xffffffffu, t11, 16);
                if (l < 16) {
                    // d = mt*16+grp (grp<4): quad pos = grp*8 + mt*4 (ks=2mt)
                    // d = mt*16+8+grp:       quad pos = grp*8 + mt*4 + 2 (ks=2mt+1)
                    float* y0 = Y + (((size_t)b * NH + head) * T_DIM + c) * HD;
                    float* y1 = y0 + HD;
                    int o0 = grp * 8 + mt * 4;
                    int o1 = o0 + 2;
                    *(float2*)&y0[o0] = make_float2(u2f(t00), u2f(u00));
                    *(float2*)&y1[o0] = make_float2(u2f(t01), u2f(u01));
                    *(float2*)&y0[o1] = make_float2(u2f(t10), u2f(u10));
                    *(float2*)&y1[o1] = make_float2(u2f(t11), u2f(u11));
                }
            } else {
                // V quad per 32-token block: token c (u=2tig) at
                // (c&~31) + tig*8 + ((c>>3)&3)*2
                int d0 = mt * 16 + grp, d1 = d0 + 8;
                int cq = (c & ~31) + tig * 8 + ((c >> 3) & 3) * 2;
                float* z0 = Y + (((size_t)b * NH + head) * HD + d0) * T_DIM + cq;
                float* z1 = Y + (((size_t)b * NH + head) * HD + d1) * T_DIM + cq;
                *(float2*)z0 = make_float2(u2f(t00), u2f(t01));
                *(float2*)z1 = make_float2(u2f(t10), u2f(t11));
            }
        }
    }
}

// ---------------------------------------------------------------------------
// Output projection: Y[B,E,T] = Wo @ ao + bo.  Quad W + quad ao (LDS.128/LDG.128).
// ---------------------------------------------------------------------------
__global__ __launch_bounds__(256) void proj_out_kernel(
    const float* __restrict__ X, const float* __restrict__ Wo_p,
    const float* __restrict__ bias, float* __restrict__ Y)
{
    __shared__ __align__(16) float Ws[64][36];
    const int b  = blockIdx.z;
    const int m0 = blockIdx.y * 64;
    const int n0 = blockIdx.x * 128;
    const int tid = threadIdx.x;
    const int w = tid >> 5, l = tid & 31;
    const int wm = w >> 2, wn = w & 3;
    const int grp = l >> 2, tig = l & 3;

    float acc[2][4][4];
    #pragma unroll
    for (int mt = 0; mt < 2; mt++)
        #pragma unroll
        for (int nt = 0; nt < 4; nt++)
            #pragma unroll
            for (int j = 0; j < 4; j++) acc[mt][nt][j] = 0.f;

    for (int k0 = 0; k0 < E_DIM; k0 += 32) {
        __syncthreads();
        #pragma unroll
        for (int j = 0; j < 2; j++) {
            int idx = tid + j * 256;
            int r = idx >> 3, c4 = (idx & 7) * 4;
            *(float4*)&Ws[r][c4] = *(const float4*)&Wo_p[(size_t)(m0 + r) * E_DIM + k0 + c4];
        }
        __syncthreads();

        const int head = k0 >> 5;
        const float* xb1 = X + (((size_t)b * NH + head) * T_DIM + n0 + wn * 32 + grp) * HD;

        const float* wb = &Ws[wm * 32 + grp][tig * 8];
        uint4 wA  = *(const uint4*)(wb);
        uint4 wAb = *(const uint4*)(wb + 4);
        uint4 wB  = *(const uint4*)(wb + 8 * 36);
        uint4 wBb = *(const uint4*)(wb + 8 * 36 + 4);
        uint4 wC  = *(const uint4*)(wb + 16 * 36);
        uint4 wCb = *(const uint4*)(wb + 16 * 36 + 4);
        uint4 wD  = *(const uint4*)(wb + 24 * 36);
        uint4 wDb = *(const uint4*)(wb + 24 * 36 + 4);
        uint32_t a0[4][4] = {{wA.x, wB.x, wA.y, wB.y}, {wA.z, wB.z, wA.w, wB.w},
                             {wAb.x, wBb.x, wAb.y, wBb.y}, {wAb.z, wBb.z, wAb.w, wBb.w}};
        uint32_t a1[4][4] = {{wC.x, wD.x, wC.y, wD.y}, {wC.z, wD.z, wC.w, wD.w},
                             {wCb.x, wDb.x, wCb.y, wDb.y}, {wCb.z, wDb.z, wCb.w, wDb.w}};

        #pragma unroll
        for (int nt = 0; nt < 4; nt++) {
            const float* xr = xb1 + (size_t)nt * 8 * HD + tig * 8;
            uint4 x0 = *(const uint4*)(xr);
            uint4 x1 = *(const uint4*)(xr + 4);
            mma16n8k8(acc[0][nt], a0[0], x0.x, x0.y);
            mma16n8k8(acc[1][nt], a1[0], x0.x, x0.y);
            mma16n8k8(acc[0][nt], a0[1], x0.z, x0.w);
            mma16n8k8(acc[1][nt], a1[1], x0.z, x0.w);
            mma16n8k8(acc[0][nt], a0[2], x1.x, x1.y);
            mma16n8k8(acc[1][nt], a1[2], x1.x, x1.y);
            mma16n8k8(acc[0][nt], a0[3], x1.z, x1.w);
            mma16n8k8(acc[1][nt], a1[3], x1.z, x1.w);
        }
    }

    #pragma unroll
    for (int mt = 0; mt < 2; mt++) {
        int r0 = m0 + wm * 32 + mt * 16 + grp;
        int r1 = r0 + 8;
        float bv0 = bias[r0], bv1 = bias[r1];
        #pragma unroll
        for (int nt = 0; nt < 4; nt++) {
            int c = n0 + wn * 32 + nt * 8 + 2 * tig;
            *(float2*)&Y[((size_t)b * E_DIM + r0) * T_DIM + c] =
                make_float2(acc[mt][nt][0] + bv0, acc[mt][nt][1] + bv0);
            *(float2*)&Y[((size_t)b * E_DIM + r1) * T_DIM + c] =
                make_float2(acc[mt][nt][2] + bv1, acc[mt][nt][3] + bv1);
        }
    }
}

// ---------------------------------------------------------------------------
// Warp-MMA (tf32) flash attention — quad layouts, double-buffered staging.
// Block 256 thr (8 warps), q-tile 128 (16 q rows/warp), key tiles of 64.
// ---------------------------------------------------------------------------
#define ATTN_STAGE(S0, BUF) do {                                               \
    _Pragma("unroll")                                                          \
    for (int j = 0; j < 2; j++) {                                              \
        int idx = tid + j * 256;                                               \
        int r = idx >> 3, seg = idx & 7;                                       \
        cp_async16(ks_a + ((BUF) * 64 * 36 + r * 36 + seg * 4) * 4,            \
                   K + ((size_t)bh * T_DIM + (S0) + r) * HD + seg * 4);        \
    }                                                                          \
    _Pragma("unroll")                                                          \
    for (int j = 0; j < 2; j++) {                                              \
        int idx = tid + j * 256;                                               \
        int d = idx >> 4, seg = idx & 15;                                      \
        cp_async16(vt_a + ((BUF) * 32 * 68 + d * 68 + seg * 4) * 4,            \
                   V + ((size_t)bh * HD + d) * T_DIM + (S0) + seg * 4);        \
    }                                                                          \
    CP_COMMIT();                                                               \
} while (0)

__global__ __launch_bounds__(256, 2) void attn_mma_kernel(
    const float* __restrict__ Q, const float* __restrict__ K,
    const float* __restrict__ V, const float* __restrict__ mask,
    float* __restrict__ O)
{
    __shared__ __align__(16) float Ks[2][64][36];   // [buf][s][k quad]
    __shared__ __align__(16) float Vt[2][32][68];   // [buf][d][s quad-32]

    const int bh  = blockIdx.y;
    const int q0  = blockIdx.x * 128;
    const int tid = threadIdx.x;
    const int w   = tid >> 5;
    const int l   = tid & 31;
    const int grp = l >> 2;
    const int tig = l & 3;

    const uint32_t ks_a = smem_u32(&Ks[0][0][0]);
    const uint32_t vt_a = smem_u32(&Vt[0][0][0]);

    // ---- Q fragments: 4x LDG.128 (quad layout) ----
    uint32_t qa[4][4];
    {
        const float* Qb = Q + ((size_t)bh * T_DIM + q0 + w * 16) * HD;
        uint4 q00 = *(const uint4*)(Qb + (size_t)grp * HD + tig * 8);
        uint4 q01 = *(const uint4*)(Qb + (size_t)grp * HD + tig * 8 + 4);
        uint4 q10 = *(const uint4*)(Qb + (size_t)(grp + 8) * HD + tig * 8);
        uint4 q11 = *(const uint4*)(Qb + (size_t)(grp + 8) * HD + tig * 8 + 4);
        qa[0][0] = q00.x; qa[0][1] = q10.x; qa[0][2] = q00.y; qa[0][3] = q10.y;
        qa[1][0] = q00.z; qa[1][1] = q10.z; qa[1][2] = q00.w; qa[1][3] = q10.w;
        qa[2][0] = q01.x; qa[2][1] = q11.x; qa[2][2] = q01.y; qa[2][3] = q11.y;
        qa[3][0] = q01.z; qa[3][1] = q11.z; qa[3][2] = q01.w; qa[3][3] = q11.w;
    }

    float o_[4][4];
    #pragma unroll
    for (int nt = 0; nt < 4; nt++)
        #pragma unroll
        for (int j = 0; j < 4; j++) o_[nt][j] = 0.f;

    float m0r = -CUDART_INF_F, m1r = -CUDART_INF_F, l0r = 0.f, l1r = 0.f;

    const float* mr0 = mask + (size_t)(q0 + w * 16 + grp) * T_DIM;
    const float* mr1 = mr0 + 8 * T_DIM;

    ATTN_STAGE(0, 0);

    for (int it = 0; it < 16; it++) {
        const int s0 = it * 64;
        const int buf = it & 1;
        __syncthreads();   // prior compute done: safe to overwrite buf^1
        if (it < 15) ATTN_STAGE(s0 + 64, buf ^ 1);

        // ---- mask preload (pre-scaled by log2e) into MMA1 accumulators ----
        float sc[8][4];
        #pragma unroll
        for (int nt = 0; nt < 8; nt++) {
            float2 mk0 = __ldg((const float2*)&mr0[s0 + nt * 8 + 2 * tig]);
            float2 mk1 = __ldg((const float2*)&mr1[s0 + nt * 8 + 2 * tig]);
            sc[nt][0] = mk0.x; sc[nt][1] = mk0.y;
            sc[nt][2] = mk1.x; sc[nt][3] = mk1.y;
        }

        if (it < 15) CP_WAIT1(); else CP_WAIT0();
        __syncthreads();

        // ---- MMA1: sc += Q' K^T (quad: 2x LDS.128 per nt) ----
        #pragma unroll
        for (int nt = 0; nt < 8; nt++) {
            const float* krow = &Ks[buf][nt * 8 + grp][tig * 8];
            uint4 b01 = *(const uint4*)(krow);
            uint4 b23 = *(const uint4*)(krow + 4);
            mma16n8k8(sc[nt], qa[0], b01.x, b01.y);
            mma16n8k8(sc[nt], qa[1], b01.z, b01.w);
            mma16n8k8(sc[nt], qa[2], b23.x, b23.y);
            mma16n8k8(sc[nt], qa[3], b23.z, b23.w);
        }

        // ---- row max (log2 domain) ----
        float mx0 = -CUDART_INF_F, mx1 = -CUDART_INF_F;
        #pragma unroll
        for (int nt = 0; nt < 8; nt++) {
            mx0 = fmaxf(mx0, fmaxf(sc[nt][0], sc[nt][1]));
            mx1 = fmaxf(mx1, fmaxf(sc[nt][2], sc[nt][3]));
        }
        mx0 = fmaxf(mx0, __shfl_xor_sync(0xffffffffu, mx0, 1));
        mx0 = fmaxf(mx0, __shfl_xor_sync(0xffffffffu, mx0, 2));
        mx1 = fmaxf(mx1, __shfl_xor_sync(0xffffffffu, mx1, 1));
        mx1 = fmaxf(mx1, __shfl_xor_sync(0xffffffffu, mx1, 2));

        float mn0 = fmaxf(m0r, mx0), mn1 = fmaxf(m1r, mx1);
        float corr0 = ex2(m0r - mn0), corr1 = ex2(m1r - mn1);
        m0r = mn0; m1r = mn1;
        float sum0 = 0.f, sum1 = 0.f;

        // ---- exp2 in place (P stays in sc registers, raw fp32 bits for MMA2) ----
        #pragma unroll
        for (int nt = 0; nt < 8; nt++) {
            float p0 = ex2(sc[nt][0] - mn0);
            float p1 = ex2(sc[nt][1] - mn0);
            float p2 = ex2(sc[nt][2] - mn1);
            float p3 = ex2(sc[nt][3] - mn1);
            sum0 += p0 + p1;  sum1 += p2 + p3;
            sc[nt][0] = p0; sc[nt][1] = p1;
            sc[nt][2] = p2; sc[nt][3] = p3;
        }
        sum0 += __shfl_xor_sync(0xffffffffu, sum0, 1);
        sum0 += __shfl_xor_sync(0xffffffffu, sum0, 2);
        sum1 += __shfl_xor_sync(0xffffffffu, sum1, 1);
        sum1 += __shfl_xor_sync(0xffffffffu, sum1, 2);
        l0r = l0r * corr0 + sum0;
        l1r = l1r * corr1 + sum1;

        #pragma unroll
        for (int nt = 0; nt < 4; nt++) {
            o_[nt][0] *= corr0; o_[nt][1] *= corr0;
            o_[nt][2] *= corr1; o_[nt][3] *= corr1;
        }

        // ---- MMA2: O += P V (quad-32: 4x LDS.128 per nt for all 8 ks) ----
        #pragma unroll
        for (int nt = 0; nt < 4; nt++) {
            const float* vrow = &Vt[buf][nt * 8 + grp][tig * 8];
            uint4 v0 = *(const uint4*)(vrow);
            uint4 v1 = *(const uint4*)(vrow + 4);
            uint4 v2 = *(const uint4*)(vrow + 32);
            uint4 v3 = *(const uint4*)(vrow + 36);
            #define PV(KS, B0, B1) {                                           \
                uint32_t a_[4] = {__float_as_uint(sc[KS][0]),                  \
                                  __float_as_uint(sc[KS][2]),                  \
                                  __float_as_uint(sc[KS][1]),                  \
                                  __float_as_uint(sc[KS][3])};                 \
                mma16n8k8(o_[nt], a_, B0, B1); }
            PV(0, v0.x, v0.y); PV(1, v0.z, v0.w);
            PV(2, v1.x, v1.y); PV(3, v1.z, v1.w);
            PV(4, v2.x, v2.y); PV(5, v2.z, v2.w);
            PV(6, v3.x, v3.y); PV(7, v3.z, v3.w);
            #undef PV
        }
    }

    // ---- epilogue: ao tf32 quad [bh][t][qq(d)] ----
    float i0 = 1.f / l0r, i1 = 1.f / l1r;
    #pragma unroll
    for (int nt = 0; nt < 4; nt++) {
        uint32_t t0 = f2tf(o_[nt][0] * i0), t1 = f2tf(o_[nt][1] * i0);
        uint32_t t2 = f2tf(o_[nt][2] * i1), t3 = f2tf(o_[nt][3] * i1);
        uint32_t u0 = __shfl_xor_sync(0xffffffffu, t0, 2);
        uint32_t u1 = __shfl_xor_sync(0xffffffffu, t1, 2);
        uint32_t u2 = __shfl_xor_sync(0xffffffffu, t2, 2);
        uint32_t u3 = __shfl_xor_sync(0xffffffffu, t3, 2);
        if (tig < 2) {
            // pairs (d, d+4): d = nt*8+2tig -> pos 16tig+2nt; d+1 -> pos 16tig+8+2nt
            size_t r0 = (size_t)bh * T_DIM + q0 + w * 16 + grp;
            float* z0 = O + r0 * HD;
            float* z1 = z0 + 8 * HD;
            int p0 = 16 * tig + 2 * nt;
            int p1 = p0 + 8;
            *(float2*)(z0 + p0) = make_float2(u2f(t0), u2f(u0));
            *(float2*)(z0 + p1) = make_float2(u2f(t1), u2f(u1));
            *(float2*)(z1 + p0) = make_float2(u2f(t2), u2f(u2));
            *(float2*)(z1 + p1) = make_float2(u2f(t3), u2f(u3));
        }
    }
}

// ---------------------------------------------------------------------------
extern "C" void kernel_launch(void* const* d_in, const int* in_sizes, int n_in,
                              void* d_out, int out_size)
{
    // metadata order: 0:query 1:key 2:value 3:attn_mask
    //                 4:Wq 5:Wk 6:Wv 7:Wo  8:bq 9:bk 10:bv 11:bo
    const float* query = (const float*)d_in[0];
    const float* key   = (const float*)d_in[1];
    const float* value = (const float*)d_in[2];
    const float* mask  = (const float*)d_in[3];
    const float* Wq    = (const float*)d_in[4];
    const float* Wk    = (const float*)d_in[5];
    const float* Wv    = (const float*)d_in[6];
    const float* Wo    = (const float*)d_in[7];
    const float* bq    = (const float*)d_in[8];
    const float* bk    = (const float*)d_in[9];
    const float* bv    = (const float*)d_in[10];
    const float* bo    = (const float*)d_in[11];
    float* out = (float*)d_out;

    static float *q_buf = nullptr, *k_buf, *v_buf, *ao_buf, *xt, *wp, *mk;
    if (!q_buf) {
        void* p;
        cudaGetSymbolAddress(&p, g_q);   q_buf  = (float*)p;
        cudaGetSymbolAddress(&p, g_k);   k_buf  = (float*)p;
        cudaGetSymbolAddress(&p, g_v);   v_buf  = (float*)p;
        cudaGetSymbolAddress(&p, g_ao);  ao_buf = (float*)p;
        cudaGetSymbolAddress(&p, g_xt);  xt = (float*)p;
        cudaGetSymbolAddress(&p, g_wp);  wp = (float*)p;
        cudaGetSymbolAddress(&p, g_msk); mk = (float*)p;
        cudaFuncSetAttribute(proj_qkv_kernel,
                             cudaFuncAttributeMaxDynamicSharedMemorySize, 92160);
    }

    // 32^-0.5 * log2(e): log2-domain softmax, folded into Q projection
    const float scale = 0.17677669529663687f * 1.4426950408889634f;

    // 1) mask pre-scale (log2 domain)
    mcvt_kernel<<<T_DIM * T_DIM / (256 * 4), 256>>>(mask, mk);

    // 2) weight pre-convert (quad tf32)
    wcvt_kernel<<<dim3(E_DIM, 4), E_DIM / 4>>>(Wq, Wk, Wv, Wo, wp);

    // 3) input transpose+convert -> [tensor][b][t][qq(e)]
    xt_kernel<<<dim3(T_DIM / 64, E_DIM / 64, 24), 256>>>(query, key, value, xt);

    // 4) QKV projections (cp.async double-buffered, quad frags)
    proj_qkv_kernel<<<dim3(T_DIM / 256, E_DIM / 64, 24), 256, 92160>>>(
        xt, wp, bq, bk, bv, q_buf, k_buf, v_buf, scale);

    // 5) attention (double-buffered staging)
    attn_mma_kernel<<<dim3(T_DIM / 128, BHTOT), 256>>>(q_buf, k_buf, v_buf, mk, ao_buf);

    // 6) output projection
    proj_out_kernel<<<dim3(T_DIM / 128, E_DIM / 64, B_DIM), 256>>>(
        ao_buf, wp + 3 * E_DIM * E_DIM, bo, out);
}